// round 2
// baseline (speedup 1.0000x reference)
#include <cuda_runtime.h>
#include <cuda_bf16.h>

#define B 64
#define L 1024
#define D 1024
#define S 32

#define DP 8            // number of d-partitions (CTAs along d)
#define DW (D / DP)     // 128 floats per partition
#define TPB 128         // threads per block for k_accum
#define UNROLL 8

// Scratch (written fully each launch; no init kernel needed, no atomics to gmem)
__device__ float g_sum[B * S * D];   // 8 MB  segment sums
__device__ float g_cnt[B * S];       // per-(b,s) token counts
__device__ float g_cos[B * S];       // per-(b,s) cosine similarity

// ---------------------------------------------------------------------------
// Kernel 1: segment sums. blockIdx = (d-partition, batch).
// Each thread owns one d-column of the [S][DW] shared accumulator -> the
// label-indexed scatter-add is conflict-free and race-free.
// ---------------------------------------------------------------------------
__global__ __launch_bounds__(TPB) void k_accum(const int* __restrict__ attr,
                                               const float* __restrict__ text) {
    __shared__ float acc[S * DW];   // 16 KB
    __shared__ int   slab[L];       // 4 KB  (label-1 per token; -1 = skip)
    __shared__ int   scnt[S];

    const int dp  = blockIdx.x;
    const int b   = blockIdx.y;
    const int tid = threadIdx.x;

    // zero accumulator
    #pragma unroll
    for (int i = tid; i < S * DW; i += TPB) acc[i] = 0.0f;
    if (tid < S) scnt[tid] = 0;

    // stage labels in shared
    const int* ab = attr + b * L;
    for (int i = tid; i < L; i += TPB) slab[i] = ab[i] - 1;
    __syncthreads();

    // main streaming loop: 1024 tokens, unroll 8, front-batched loads
    const float* tb = text + (size_t)b * L * D + (size_t)dp * DW + tid;
    #pragma unroll 1
    for (int l = 0; l < L; l += UNROLL) {
        float v[UNROLL];
        int   s[UNROLL];
        #pragma unroll
        for (int u = 0; u < UNROLL; u++) {
            v[u] = __ldcs(tb + (size_t)(l + u) * D);  // streaming: no reuse
            s[u] = slab[l + u];
        }
        #pragma unroll
        for (int u = 0; u < UNROLL; u++) {
            if (s[u] >= 0) acc[s[u] * DW + tid] += v[u];  // uniform s per warp
        }
    }

    // counts: only the dp==0 CTA for this batch (shared atomics, deterministic)
    if (dp == 0) {
        for (int i = tid; i < L; i += TPB) {
            int s = slab[i];
            if (s >= 0) atomicAdd(&scnt[s], 1);
        }
    }
    __syncthreads();

    // write this CTA's d-slice of every segment sum (each element written once)
    float* outp = g_sum + (size_t)b * S * D + (size_t)dp * DW + tid;
    #pragma unroll
    for (int s = 0; s < S; s++) outp[(size_t)s * D] = acc[s * DW + tid];
    if (dp == 0 && tid < S) g_cnt[b * S + tid] = (float)scnt[tid];
}

// ---------------------------------------------------------------------------
// Kernel 2: per-(b,s) cosine similarity. One 128-thread block per (b,s).
// ---------------------------------------------------------------------------
__global__ __launch_bounds__(128) void k_cos(const float* __restrict__ Vgs) {
    const int bs  = blockIdx.x;       // b*S + s  (matches Vgs / g_sum layout)
    const int tid = threadIdx.x;

    const float* vg = Vgs   + (size_t)bs * D;
    const float* sm = g_sum + (size_t)bs * D;
    const float cnt = g_cnt[bs];
    const float inv = (cnt > 0.0f) ? (1.0f / cnt) : 0.0f;

    float dvm = 0.0f, dmm = 0.0f, dvv = 0.0f;
    #pragma unroll 2
    for (int d = tid; d < D; d += 128) {
        float m = sm[d] * inv;
        float v = vg[d];
        dvm = fmaf(v, m, dvm);
        dmm = fmaf(m, m, dmm);
        dvv = fmaf(v, v, dvv);
    }
    // warp reduce
    #pragma unroll
    for (int o = 16; o > 0; o >>= 1) {
        dvm += __shfl_down_sync(0xFFFFFFFFu, dvm, o);
        dmm += __shfl_down_sync(0xFFFFFFFFu, dmm, o);
        dvv += __shfl_down_sync(0xFFFFFFFFu, dvv, o);
    }
    __shared__ float r0[4], r1[4], r2[4];
    const int w = tid >> 5, lane = tid & 31;
    if (lane == 0) { r0[w] = dvm; r1[w] = dmm; r2[w] = dvv; }
    __syncthreads();
    if (tid == 0) {
        float a = r0[0] + r0[1] + r0[2] + r0[3];
        float m2 = r1[0] + r1[1] + r1[2] + r1[3];
        float v2 = r2[0] + r2[1] + r2[2] + r2[3];
        float denom = fmaxf(sqrtf(v2) * sqrtf(m2), 1e-8f);
        g_cos[bs] = a / denom;
    }
}

// ---------------------------------------------------------------------------
// Kernel 3: deterministic reduction of 2048 cosines -> scalar loss.
// ---------------------------------------------------------------------------
__global__ __launch_bounds__(1024) void k_final(float* __restrict__ out) {
    const int tid = threadIdx.x;
    float v = g_cos[tid] + g_cos[tid + 1024];
    #pragma unroll
    for (int o = 16; o > 0; o >>= 1) v += __shfl_down_sync(0xFFFFFFFFu, v, o);
    __shared__ float sh[32];
    if ((tid & 31) == 0) sh[tid >> 5] = v;
    __syncthreads();
    if (tid < 32) {
        float x = sh[tid];
        #pragma unroll
        for (int o = 16; o > 0; o >>= 1) x += __shfl_down_sync(0xFFFFFFFFu, x, o);
        if (tid == 0) out[0] = 1.0f - x / (float)(B * S);
    }
}

// ---------------------------------------------------------------------------
// Launch: attributes [B,L] int32, text_feats [B,L,D] f32, Vgs [B,S,D] f32
// ---------------------------------------------------------------------------
extern "C" void kernel_launch(void* const* d_in, const int* in_sizes, int n_in,
                              void* d_out, int out_size) {
    const int*   attr = (const int*)d_in[0];
    const float* text = (const float*)d_in[1];
    const float* vgs  = (const float*)d_in[2];
    float*       out  = (float*)d_out;

    dim3 g1(DP, B);
    k_accum<<<g1, TPB>>>(attr, text);
    k_cos<<<B * S, 128>>>(vgs);
    k_final<<<1, 1024>>>(out);
}

// round 3
// speedup vs baseline: 1.3144x; 1.3144x over previous
#include <cuda_runtime.h>
#include <cuda_bf16.h>

#define B 64
#define L 1024
#define D 1024
#define S 32

#define DP 8            // d-partitions (CTAs along d)
#define DW (D / DP)     // 128 floats per partition
#define LP 4            // token-partitions (CTAs along tokens)
#define LCH (L / LP)    // 256 tokens per CTA
#define TPB 128
#define UNROLL 8

// Scratch (every element written exactly once per launch -> deterministic)
__device__ float g_part[LP * B * S * D];   // 32 MB partial segment sums
__device__ float g_cntp[B * LP * S];       // per-(b,lp,s) chunk counts
__device__ float g_cos[B * S];             // per-(b,s) cosine similarity

// ---------------------------------------------------------------------------
// Kernel 1: partial segment sums. blockIdx = (d-partition, batch, token-chunk).
// Each thread owns one d-column of the [S][DW] shared accumulator -> the
// label-indexed scatter-add is conflict-free and race-free.
// ---------------------------------------------------------------------------
__global__ __launch_bounds__(TPB) void k_accum(const int* __restrict__ attr,
                                               const float* __restrict__ text) {
    __shared__ float acc[S * DW];   // 16 KB
    __shared__ int   slab[LCH];     // 1 KB (label-1 per token; -1 = skip)
    __shared__ int   scnt[S];

    const int dp  = blockIdx.x;
    const int b   = blockIdx.y;
    const int lp  = blockIdx.z;
    const int tid = threadIdx.x;

    #pragma unroll
    for (int i = tid; i < S * DW; i += TPB) acc[i] = 0.0f;
    if (tid < S) scnt[tid] = 0;

    const int* ab = attr + b * L + lp * LCH;
    for (int i = tid; i < LCH; i += TPB) slab[i] = ab[i] - 1;
    __syncthreads();

    // stream this CTA's 256-token x 128-col tile
    const float* tb = text + (size_t)b * L * D + (size_t)lp * LCH * D
                           + (size_t)dp * DW + tid;
    #pragma unroll 1
    for (int l = 0; l < LCH; l += UNROLL) {
        float v[UNROLL];
        int   s[UNROLL];
        #pragma unroll
        for (int u = 0; u < UNROLL; u++) {
            v[u] = __ldcs(tb + (size_t)(l + u) * D);   // streaming, read-once
            s[u] = slab[l + u];
        }
        #pragma unroll
        for (int u = 0; u < UNROLL; u++) {
            if (s[u] >= 0) acc[s[u] * DW + tid] += v[u];  // uniform s per warp
        }
    }

    // per-chunk counts (dp==0 CTA only; shared atomics, deterministic)
    if (dp == 0) {
        for (int i = tid; i < LCH; i += TPB) {
            int s = slab[i];
            if (s >= 0) atomicAdd(&scnt[s], 1);
        }
    }
    __syncthreads();

    // write this CTA's d-slice of every partial segment sum (written once)
    float* outp = g_part + ((size_t)lp * B + b) * S * D + (size_t)dp * DW + tid;
    #pragma unroll
    for (int s = 0; s < S; s++) outp[(size_t)s * D] = acc[s * DW + tid];
    if (dp == 0 && tid < S) g_cntp[(b * LP + lp) * S + tid] = (float)scnt[tid];
}

// ---------------------------------------------------------------------------
// Kernel 2: per-(b,s) cosine similarity; folds the LP partials inline.
// One 128-thread block per (b,s). float4 loads.
// ---------------------------------------------------------------------------
__global__ __launch_bounds__(128) void k_cos(const float* __restrict__ Vgs) {
    const int bs  = blockIdx.x;     // b*S + s
    const int b   = bs / S;
    const int tid = threadIdx.x;

    const float4* vg = (const float4*)(Vgs + (size_t)bs * D);
    const float4* p0 = (const float4*)(g_part + ((size_t)0 * B * S + bs) * D);
    const float4* p1 = (const float4*)(g_part + ((size_t)1 * B * S + bs) * D);
    const float4* p2 = (const float4*)(g_part + ((size_t)2 * B * S + bs) * D);
    const float4* p3 = (const float4*)(g_part + ((size_t)3 * B * S + bs) * D);

    const int sloc = bs - b * S;
    float cnt = 0.0f;
    #pragma unroll
    for (int lp = 0; lp < LP; lp++) cnt += g_cntp[(b * LP + lp) * S + sloc];
    const float inv = (cnt > 0.0f) ? (1.0f / cnt) : 0.0f;

    float dvm = 0.0f, dmm = 0.0f, dvv = 0.0f;
    #pragma unroll 2
    for (int d = tid; d < D / 4; d += 128) {
        float4 a0 = p0[d], a1 = p1[d], a2 = p2[d], a3 = p3[d];
        float4 v  = vg[d];
        float mx = (a0.x + a1.x + a2.x + a3.x) * inv;
        float my = (a0.y + a1.y + a2.y + a3.y) * inv;
        float mz = (a0.z + a1.z + a2.z + a3.z) * inv;
        float mw = (a0.w + a1.w + a2.w + a3.w) * inv;
        dvm = fmaf(v.x, mx, fmaf(v.y, my, fmaf(v.z, mz, fmaf(v.w, mw, dvm))));
        dmm = fmaf(mx, mx, fmaf(my, my, fmaf(mz, mz, fmaf(mw, mw, dmm))));
        dvv = fmaf(v.x, v.x, fmaf(v.y, v.y, fmaf(v.z, v.z, fmaf(v.w, v.w, dvv))));
    }
    #pragma unroll
    for (int o = 16; o > 0; o >>= 1) {
        dvm += __shfl_down_sync(0xFFFFFFFFu, dvm, o);
        dmm += __shfl_down_sync(0xFFFFFFFFu, dmm, o);
        dvv += __shfl_down_sync(0xFFFFFFFFu, dvv, o);
    }
    __shared__ float r0[4], r1[4], r2[4];
    const int w = tid >> 5, lane = tid & 31;
    if (lane == 0) { r0[w] = dvm; r1[w] = dmm; r2[w] = dvv; }
    __syncthreads();
    if (tid == 0) {
        float a  = r0[0] + r0[1] + r0[2] + r0[3];
        float m2 = r1[0] + r1[1] + r1[2] + r1[3];
        float v2 = r2[0] + r2[1] + r2[2] + r2[3];
        float denom = fmaxf(sqrtf(v2) * sqrtf(m2), 1e-8f);
        g_cos[bs] = a / denom;
    }
}

// ---------------------------------------------------------------------------
// Kernel 3: deterministic reduction of 2048 cosines -> scalar loss.
// ---------------------------------------------------------------------------
__global__ __launch_bounds__(1024) void k_final(float* __restrict__ out) {
    const int tid = threadIdx.x;
    float v = g_cos[tid] + g_cos[tid + 1024];
    #pragma unroll
    for (int o = 16; o > 0; o >>= 1) v += __shfl_down_sync(0xFFFFFFFFu, v, o);
    __shared__ float sh[32];
    if ((tid & 31) == 0) sh[tid >> 5] = v;
    __syncthreads();
    if (tid < 32) {
        float x = sh[tid];
        #pragma unroll
        for (int o = 16; o > 0; o >>= 1) x += __shfl_down_sync(0xFFFFFFFFu, x, o);
        if (tid == 0) out[0] = 1.0f - x / (float)(B * S);
    }
}

// ---------------------------------------------------------------------------
extern "C" void kernel_launch(void* const* d_in, const int* in_sizes, int n_in,
                              void* d_out, int out_size) {
    const int*   attr = (const int*)d_in[0];
    const float* text = (const float*)d_in[1];
    const float* vgs  = (const float*)d_in[2];
    float*       out  = (float*)d_out;

    dim3 g1(DP, B, LP);
    k_accum<<<g1, TPB>>>(attr, text);
    k_cos<<<B * S, 128>>>(vgs);
    k_final<<<1, 1024>>>(out);
}